// round 2
// baseline (speedup 1.0000x reference)
#include <cuda_runtime.h>
#include <cuda_bf16.h>
#include <cstdint>

// RBF_Conv2d: x (16,1,256,256) f32, w (64,1,5,5) f32 -> out (16,64,252,252) f32
// out[b,o,h,w] = exp(-0.5 * d2 / var_hw),  d2 = max(||patch-w||^2, 1e-12)
// var_hw = sample var (ddof=1) of dist over the (B*O)=1024 matrix at pixel (h,w)

#define B_  16
#define O_  64
#define HO  252
#define WO  252
#define WT  12      // w-pixels per block (252 = 21*12, no tail)
#define WIN 16      // window width held in smem/regs (WT + 4)

__global__ __launch_bounds__(256, 2)
void rbf_conv2d_kernel(const float* __restrict__ x,
                       const float* __restrict__ w,
                       float* __restrict__ out)
{
    __shared__ float xs[B_][5][WIN];     // x window: 16 b x 5 rows x 16 cols
    __shared__ float ws[25][O_];         // weights transposed: [k][o]
    __shared__ float pns[B_][WT];        // patch norms per (b, w)
    __shared__ float red[8][WT];         // per-warp partial sums
    __shared__ float mean_s[WT];
    __shared__ float cinv_s[WT];

    const int tid = threadIdx.x;
    const int h   = blockIdx.y;
    const int w0  = blockIdx.x * WT;

    // ---- load weights transposed: ws[k][o] = w[o*25+k] ----
    for (int i = tid; i < 25 * O_; i += 256) {
        int k = i >> 6, o = i & 63;
        ws[k][o] = w[o * 25 + k];
    }
    // ---- load x window: rows h..h+4, cols w0..w0+15 (always in-bounds: 252+4-1=255) ----
    for (int i = tid; i < B_ * 5 * WIN; i += 256) {
        int b = i / (5 * WIN);
        int r = (i / WIN) % 5;
        int c = i & (WIN - 1);
        xs[b][r][c] = x[b * 65536 + (h + r) * 256 + (w0 + c)];
    }
    __syncthreads();

    // ---- patch norms pn[b][wi] = sum_k patch^2 ----
    if (tid < B_ * WT) {
        int b = tid / WT, wi = tid % WT;
        float s = 0.f;
        #pragma unroll
        for (int kh = 0; kh < 5; kh++)
            #pragma unroll
            for (int kw = 0; kw < 5; kw++) {
                float v = xs[b][kh][wi + kw];
                s = fmaf(v, v, s);
            }
        pns[b][wi] = s;
    }
    __syncthreads();

    // ---- thread tile: 2 b x 2 o x 12 w ----
    const int bt = tid >> 5;        // 0..7  (fixed per warp -> broadcast LDS)
    const int ot = tid & 31;        // 0..31
    const int b0 = bt * 2;
    const int o0 = ot * 2;

    float acc[2][2][WT];
    #pragma unroll
    for (int i = 0; i < 2; i++)
        #pragma unroll
        for (int j = 0; j < 2; j++)
            #pragma unroll
            for (int wi = 0; wi < WT; wi++) acc[i][j][wi] = 0.f;

    float wn0 = 0.f, wn1 = 0.f;

    #pragma unroll
    for (int kh = 0; kh < 5; kh++) {
        // register sliding window for the two b rows
        float win0[WIN], win1[WIN];
        #pragma unroll
        for (int c = 0; c < WIN; c += 4) {
            float4 a = *(const float4*)&xs[b0][kh][c];
            win0[c] = a.x; win0[c + 1] = a.y; win0[c + 2] = a.z; win0[c + 3] = a.w;
            float4 bq = *(const float4*)&xs[b0 + 1][kh][c];
            win1[c] = bq.x; win1[c + 1] = bq.y; win1[c + 2] = bq.z; win1[c + 3] = bq.w;
        }
        #pragma unroll
        for (int kw = 0; kw < 5; kw++) {
            const int k = kh * 5 + kw;
            float2 wv = *(const float2*)&ws[k][o0];
            wn0 = fmaf(wv.x, wv.x, wn0);
            wn1 = fmaf(wv.y, wv.y, wn1);
            #pragma unroll
            for (int wi = 0; wi < WT; wi++) {
                float p0 = win0[wi + kw];
                float p1 = win1[wi + kw];
                acc[0][0][wi] = fmaf(p0, wv.x, acc[0][0][wi]);
                acc[0][1][wi] = fmaf(p0, wv.y, acc[0][1][wi]);
                acc[1][0][wi] = fmaf(p1, wv.x, acc[1][0][wi]);
                acc[1][1][wi] = fmaf(p1, wv.y, acc[1][1][wi]);
            }
        }
    }

    // ---- dist = sqrt(max(pn + wn - 2*cross, 1e-12)); local per-w sums ----
    float sums[WT];
    #pragma unroll
    for (int wi = 0; wi < WT; wi++) sums[wi] = 0.f;

    #pragma unroll
    for (int i = 0; i < 2; i++) {
        float pnv[WT];
        #pragma unroll
        for (int wi = 0; wi < WT; wi++) pnv[wi] = pns[b0 + i][wi];
        #pragma unroll
        for (int j = 0; j < 2; j++) {
            const float wn = j ? wn1 : wn0;
            #pragma unroll
            for (int wi = 0; wi < WT; wi++) {
                float d2 = pnv[wi] + wn - 2.f * acc[i][j][wi];
                d2 = fmaxf(d2, 1e-12f);
                float d = sqrtf(d2);
                acc[i][j][wi] = d;           // keep dist in-place
                sums[wi] += d;
            }
        }
    }

    // ---- pass 1: mean over 1024 values per w ----
    #pragma unroll
    for (int off = 16; off; off >>= 1)
        #pragma unroll
        for (int wi = 0; wi < WT; wi++)
            sums[wi] += __shfl_xor_sync(0xffffffffu, sums[wi], off);
    if (ot == 0) {
        #pragma unroll
        for (int wi = 0; wi < WT; wi++) red[bt][wi] = sums[wi];
    }
    __syncthreads();
    if (tid < WT) {
        float s = 0.f;
        #pragma unroll
        for (int r = 0; r < 8; r++) s += red[r][tid];
        mean_s[tid] = s * (1.0f / 1024.0f);
    }
    __syncthreads();

    // ---- pass 2: sum (d - mean)^2 ----
    float mloc[WT];
    #pragma unroll
    for (int wi = 0; wi < WT; wi++) { mloc[wi] = mean_s[wi]; sums[wi] = 0.f; }
    #pragma unroll
    for (int i = 0; i < 2; i++)
        #pragma unroll
        for (int j = 0; j < 2; j++)
            #pragma unroll
            for (int wi = 0; wi < WT; wi++) {
                float dd = acc[i][j][wi] - mloc[wi];
                sums[wi] = fmaf(dd, dd, sums[wi]);
            }
    #pragma unroll
    for (int off = 16; off; off >>= 1)
        #pragma unroll
        for (int wi = 0; wi < WT; wi++)
            sums[wi] += __shfl_xor_sync(0xffffffffu, sums[wi], off);
    __syncthreads();   // all pass-1 readers of red[] are done (they were pre-pass-2)
    if (ot == 0) {
        #pragma unroll
        for (int wi = 0; wi < WT; wi++) red[bt][wi] = sums[wi];
    }
    __syncthreads();
    if (tid < WT) {
        float s = 0.f;
        #pragma unroll
        for (int r = 0; r < 8; r++) s += red[r][tid];
        float var = s * (1.0f / 1023.0f);
        // exp(-0.5*d^2/var) = exp2( d^2 * (-0.5*log2(e)/var) )
        cinv_s[tid] = -0.72134752044448170368f / var;
    }
    __syncthreads();

    float cl[WT];
    #pragma unroll
    for (int wi = 0; wi < WT; wi++) cl[wi] = cinv_s[wi];

    // ---- write out: per (b,o) 12 contiguous floats (16B-aligned float4 x3) ----
    #pragma unroll
    for (int i = 0; i < 2; i++)
        #pragma unroll
        for (int j = 0; j < 2; j++) {
            size_t base = ((size_t)((b0 + i) * O_ + (o0 + j)) * HO + h) * WO + w0;
            #pragma unroll
            for (int g = 0; g < WT; g += 4) {
                float4 v;
                float d0 = acc[i][j][g + 0];
                float d1 = acc[i][j][g + 1];
                float d2v = acc[i][j][g + 2];
                float d3 = acc[i][j][g + 3];
                v.x = exp2f(cl[g + 0] * d0 * d0);
                v.y = exp2f(cl[g + 1] * d1 * d1);
                v.z = exp2f(cl[g + 2] * d2v * d2v);
                v.w = exp2f(cl[g + 3] * d3 * d3);
                *(float4*)&out[base + g] = v;
            }
        }
}

extern "C" void kernel_launch(void* const* d_in, const int* in_sizes, int n_in,
                              void* d_out, int out_size)
{
    const float* x = (const float*)d_in[0];      // (16,1,256,256)
    const float* w = (const float*)d_in[1];      // (64,1,5,5)
    float* out = (float*)d_out;                  // (16,64,252,252)

    dim3 grid(WO / WT, HO);                      // (21, 252)
    rbf_conv2d_kernel<<<grid, 256>>>(x, w, out);
}